// round 10
// baseline (speedup 1.0000x reference)
#include <cuda_runtime.h>

// BiologicalNormalization: 3 chained per-row LayerNorms (D=512), gathered
// per-sample affine params; trailing sigmoid-gated blend is the identity.
//
// R10: R7 config (128thr, lb(128,7), 2 rows/warp, 28 warps/SM) with
// HALF-WARP-PER-ROW layout: lane l (h=l>>4, j=l&15) holds row h's float4s
// at j+16k, k=0..7. Reductions confined to 16 lanes: 2 values x 4 rounds
// (vs 4 x 5) -> exposed SHFL chain cut ~45%. Param LDGs become 2-line
// half-broadcasts (lower L1 wavefront pressure). Loads remain coalesced.

#define B_DIM 2048
#define S_DIM 128
#define D_DIM 512
#define THREADS 128
#define WARPS 4
#define SPLIT 16          // blocks per sample (8 rows per block)

__global__ __launch_bounds__(THREADS, 7)
void bionorm_kernel(const float* __restrict__ x,
                    const int* __restrict__ pathway_ids,
                    const int* __restrict__ compartment_ids,
                    const int* __restrict__ cell_type_ids,
                    const float* __restrict__ pg, const float* __restrict__ pb,
                    const float* __restrict__ cg, const float* __restrict__ cb,
                    const float* __restrict__ tg, const float* __restrict__ tb,
                    float* __restrict__ out)
{
    const int blk = blockIdx.x;
    const int b = blk >> 4;            // sample
    const int lane = threadIdx.x & 31;
    const int h = lane >> 4;           // row within the warp's pair
    const int j = lane & 15;           // float4 slot within half

    const int p_id = __ldg(pathway_ids + b);
    const int c_id = __ldg(compartment_ids + b);
    const int t_id = __ldg(cell_type_ids + b);

    // Warp's 2-row tile base (in float4 units), plus this thread's offset.
    const size_t base4 = ((size_t)b * S_DIM
                        + ((blk & 15) * (WARPS * 2) + (threadIdx.x >> 5) * 2))
                        * (D_DIM / 4);
    const float4* __restrict__ xr =
        reinterpret_cast<const float4*>(x) + base4 + h * (D_DIM / 4) + j;

    // 8 independent LDG.128: this thread's 32 floats of its row.
    float4 v[8];
    #pragma unroll
    for (int k = 0; k < 8; k++)
        v[k] = xr[16 * k];

    const float inv_d = 1.0f / (float)D_DIM;
    const float eps = 1e-5f;

    #pragma unroll
    for (int p = 0; p < 3; p++) {
        // Param pointers rematerialized per pass from constant-bank bases.
        const float4* gvp;
        const float4* bvp;
        if (p == 0) {
            gvp = reinterpret_cast<const float4*>(pg + (size_t)p_id * D_DIM);
            bvp = reinterpret_cast<const float4*>(pb + (size_t)p_id * D_DIM);
        } else if (p == 1) {
            gvp = reinterpret_cast<const float4*>(cg + (size_t)c_id * D_DIM);
            bvp = reinterpret_cast<const float4*>(cb + (size_t)c_id * D_DIM);
        } else {
            gvp = reinterpret_cast<const float4*>(tg + (size_t)t_id * D_DIM);
            bvp = reinterpret_cast<const float4*>(tb + (size_t)t_id * D_DIM);
        }
        gvp += j;
        bvp += j;

        // Local stats over 32 floats, tree-shaped to shorten the chain.
        float4 s0, s1, s2, s3, q0, q1, q2, q3;
        s0.x = v[0].x + v[4].x; s0.y = v[0].y + v[4].y;
        s0.z = v[0].z + v[4].z; s0.w = v[0].w + v[4].w;
        s1.x = v[1].x + v[5].x; s1.y = v[1].y + v[5].y;
        s1.z = v[1].z + v[5].z; s1.w = v[1].w + v[5].w;
        s2.x = v[2].x + v[6].x; s2.y = v[2].y + v[6].y;
        s2.z = v[2].z + v[6].z; s2.w = v[2].w + v[6].w;
        s3.x = v[3].x + v[7].x; s3.y = v[3].y + v[7].y;
        s3.z = v[3].z + v[7].z; s3.w = v[3].w + v[7].w;

        q0.x = v[0].x * v[0].x; q0.y = v[0].y * v[0].y;
        q0.z = v[0].z * v[0].z; q0.w = v[0].w * v[0].w;
        q1.x = v[1].x * v[1].x; q1.y = v[1].y * v[1].y;
        q1.z = v[1].z * v[1].z; q1.w = v[1].w * v[1].w;
        q2.x = v[2].x * v[2].x; q2.y = v[2].y * v[2].y;
        q2.z = v[2].z * v[2].z; q2.w = v[2].w * v[2].w;
        q3.x = v[3].x * v[3].x; q3.y = v[3].y * v[3].y;
        q3.z = v[3].z * v[3].z; q3.w = v[3].w * v[3].w;
        #pragma unroll
        for (int k = 4; k < 8; k++) {
            float4* qq = (k == 4) ? &q0 : (k == 5) ? &q1 : (k == 6) ? &q2 : &q3;
            qq->x = fmaf(v[k].x, v[k].x, qq->x);
            qq->y = fmaf(v[k].y, v[k].y, qq->y);
            qq->z = fmaf(v[k].z, v[k].z, qq->z);
            qq->w = fmaf(v[k].w, v[k].w, qq->w);
        }

        s0.x += s1.x; s0.y += s1.y; s0.z += s1.z; s0.w += s1.w;
        s2.x += s3.x; s2.y += s3.y; s2.z += s3.z; s2.w += s3.w;
        q0.x += q1.x; q0.y += q1.y; q0.z += q1.z; q0.w += q1.w;
        q2.x += q3.x; q2.y += q3.y; q2.z += q3.z; q2.w += q3.w;

        float s = (s0.x + s2.x) + (s0.y + s2.y)
                + (s0.z + s2.z) + (s0.w + s2.w);
        float q = (q0.x + q2.x) + (q0.y + q2.y)
                + (q0.z + q2.z) + (q0.w + q2.w);

        // Half-warp reduction: 4 rounds, stays within lanes of this row.
        #pragma unroll
        for (int o = 8; o > 0; o >>= 1) {
            s += __shfl_xor_sync(0xffffffffu, s, o);
            q += __shfl_xor_sync(0xffffffffu, q, o);
        }

        const float mean = s * inv_d;
        const float var = fmaf(-mean, mean, q * inv_d);
        const float a = rsqrtf(var + eps);
        const float c = -mean * a;

        #pragma unroll
        for (int k = 0; k < 8; k++) {
            const float4 gg = __ldg(gvp + 16 * k);
            const float4 bb = __ldg(bvp + 16 * k);
            v[k].x = fmaf(fmaf(v[k].x, a, c), gg.x, bb.x);
            v[k].y = fmaf(fmaf(v[k].y, a, c), gg.y, bb.y);
            v[k].z = fmaf(fmaf(v[k].z, a, c), gg.z, bb.z);
            v[k].w = fmaf(fmaf(v[k].w, a, c), gg.w, bb.w);
        }
    }

    float4* __restrict__ orow =
        reinterpret_cast<float4*>(out) + base4 + h * (D_DIM / 4) + j;
    #pragma unroll
    for (int k = 0; k < 8; k++)
        orow[16 * k] = v[k];
}

extern "C" void kernel_launch(void* const* d_in, const int* in_sizes, int n_in,
                              void* d_out, int out_size)
{
    const float* x  = (const float*)d_in[0];
    const int* pid  = (const int*)d_in[1];
    const int* cid  = (const int*)d_in[2];
    const int* tid  = (const int*)d_in[3];
    const float* pg = (const float*)d_in[4];
    const float* pb = (const float*)d_in[5];
    const float* cg = (const float*)d_in[6];
    const float* cb = (const float*)d_in[7];
    const float* tg = (const float*)d_in[8];
    const float* tb = (const float*)d_in[9];
    // d_in[10] = W, d_in[11] = b : unused (gated blend is the identity)
    float* out = (float*)d_out;

    dim3 grid(B_DIM * SPLIT);
    dim3 block(THREADS);
    bionorm_kernel<<<grid, block>>>(x, pid, cid, tid,
                                    pg, pb, cg, cb, tg, tb, out);
}

// round 11
// speedup vs baseline: 1.0945x; 1.0945x over previous
#include <cuda_runtime.h>

// BiologicalNormalization: 3 chained per-row LayerNorms (D=512), gathered
// per-sample affine params; trailing sigmoid-gated blend is the identity.
//
// R11: R7 config (ROWS=2/warp, 128 thr, lb(128,7) -> 72 regs, 28 warps/SM,
// full-warp shuffle reductions, remat'd param pointers) + fused stats:
// pass p's normalize loop accumulates pass p+1's sum/sumsq, removing the
// separate stat traversal from the serial chain of passes 2 and 3.

#define B_DIM 2048
#define S_DIM 128
#define D_DIM 512
#define THREADS 128
#define WARPS 4
#define ROWS 2            // rows per warp -> 8 rows per block
#define SPLIT 16          // blocks per sample

__global__ __launch_bounds__(THREADS, 7)
void bionorm_kernel(const float* __restrict__ x,
                    const int* __restrict__ pathway_ids,
                    const int* __restrict__ compartment_ids,
                    const int* __restrict__ cell_type_ids,
                    const float* __restrict__ pg, const float* __restrict__ pb,
                    const float* __restrict__ cg, const float* __restrict__ cb,
                    const float* __restrict__ tg, const float* __restrict__ tb,
                    float* __restrict__ out)
{
    const int blk = blockIdx.x;
    const int b = blk >> 4;           // sample
    const int lane = threadIdx.x & 31;

    const int p_id = __ldg(pathway_ids + b);
    const int c_id = __ldg(compartment_ids + b);
    const int t_id = __ldg(cell_type_ids + b);

    const size_t elem0 = ((size_t)b * S_DIM
                        + ((blk & 15) * (WARPS * ROWS) + (threadIdx.x >> 5) * ROWS))
                        * D_DIM;
    const float4* __restrict__ xr = reinterpret_cast<const float4*>(x + elem0);

    // Front-batched load of 2 full rows: 8 independent LDG.128.
    float4 v[ROWS][4];
    #pragma unroll
    for (int r = 0; r < ROWS; r++)
        #pragma unroll
        for (int i = 0; i < 4; i++)
            v[r][i] = xr[r * (D_DIM / 4) + lane + 32 * i];

    const float inv_d = 1.0f / (float)D_DIM;
    const float eps = 1e-5f;

    // Pass-1 local stats (only explicit stat traversal; passes 2/3 get
    // theirs fused into the previous normalize loop).
    float sum[ROWS], sq[ROWS];
    #pragma unroll
    for (int r = 0; r < ROWS; r++) {
        float s = 0.f, q = 0.f;
        #pragma unroll
        for (int i = 0; i < 4; i++) {
            s += v[r][i].x + v[r][i].y + v[r][i].z + v[r][i].w;
            q = fmaf(v[r][i].x, v[r][i].x, q);
            q = fmaf(v[r][i].y, v[r][i].y, q);
            q = fmaf(v[r][i].z, v[r][i].z, q);
            q = fmaf(v[r][i].w, v[r][i].w, q);
        }
        sum[r] = s; sq[r] = q;
    }

    #pragma unroll
    for (int p = 0; p < 3; p++) {
        // Param pointers rematerialized per pass from constant-bank bases.
        const float4* gvp;
        const float4* bvp;
        if (p == 0) {
            gvp = reinterpret_cast<const float4*>(pg + (size_t)p_id * D_DIM);
            bvp = reinterpret_cast<const float4*>(pb + (size_t)p_id * D_DIM);
        } else if (p == 1) {
            gvp = reinterpret_cast<const float4*>(cg + (size_t)c_id * D_DIM);
            bvp = reinterpret_cast<const float4*>(cb + (size_t)c_id * D_DIM);
        } else {
            gvp = reinterpret_cast<const float4*>(tg + (size_t)t_id * D_DIM);
            bvp = reinterpret_cast<const float4*>(tb + (size_t)t_id * D_DIM);
        }

        // Warp reduction (4 independent shuffle chains, 5 rounds).
        #pragma unroll
        for (int o = 16; o > 0; o >>= 1) {
            #pragma unroll
            for (int r = 0; r < ROWS; r++) {
                sum[r] += __shfl_xor_sync(0xffffffffu, sum[r], o);
                sq[r]  += __shfl_xor_sync(0xffffffffu, sq[r],  o);
            }
        }

        // a = rstd, c = -mean*rstd  ->  normalized = fma(v, a, c)
        float a[ROWS], c[ROWS];
        #pragma unroll
        for (int r = 0; r < ROWS; r++) {
            const float mean = sum[r] * inv_d;
            const float var = fmaf(-mean, mean, sq[r] * inv_d);
            a[r] = rsqrtf(var + eps);
            c[r] = -mean * a[r];
            sum[r] = 0.f;   // become next pass's accumulators
            sq[r] = 0.f;
        }

        // Normalize + fused accumulation of next pass's stats.
        #pragma unroll
        for (int i = 0; i < 4; i++) {
            const float4 gg = __ldg(gvp + lane + 32 * i);
            const float4 bb = __ldg(bvp + lane + 32 * i);
            #pragma unroll
            for (int r = 0; r < ROWS; r++) {
                float4 y;
                y.x = fmaf(fmaf(v[r][i].x, a[r], c[r]), gg.x, bb.x);
                y.y = fmaf(fmaf(v[r][i].y, a[r], c[r]), gg.y, bb.y);
                y.z = fmaf(fmaf(v[r][i].z, a[r], c[r]), gg.z, bb.z);
                y.w = fmaf(fmaf(v[r][i].w, a[r], c[r]), gg.w, bb.w);
                v[r][i] = y;
                if (p < 2) {
                    sum[r] += (y.x + y.y) + (y.z + y.w);
                    sq[r] = fmaf(y.x, y.x, sq[r]);
                    sq[r] = fmaf(y.y, y.y, sq[r]);
                    sq[r] = fmaf(y.z, y.z, sq[r]);
                    sq[r] = fmaf(y.w, y.w, sq[r]);
                }
            }
        }
    }

    float4* __restrict__ orow = reinterpret_cast<float4*>(out + elem0);
    #pragma unroll
    for (int r = 0; r < ROWS; r++)
        #pragma unroll
        for (int i = 0; i < 4; i++)
            orow[r * (D_DIM / 4) + lane + 32 * i] = v[r][i];
}

extern "C" void kernel_launch(void* const* d_in, const int* in_sizes, int n_in,
                              void* d_out, int out_size)
{
    const float* x  = (const float*)d_in[0];
    const int* pid  = (const int*)d_in[1];
    const int* cid  = (const int*)d_in[2];
    const int* tid  = (const int*)d_in[3];
    const float* pg = (const float*)d_in[4];
    const float* pb = (const float*)d_in[5];
    const float* cg = (const float*)d_in[6];
    const float* cb = (const float*)d_in[7];
    const float* tg = (const float*)d_in[8];
    const float* tb = (const float*)d_in[9];
    // d_in[10] = W, d_in[11] = b : unused (gated blend is the identity)
    float* out = (float*)d_out;

    dim3 grid(B_DIM * SPLIT);
    dim3 block(THREADS);
    bionorm_kernel<<<grid, block>>>(x, pid, cid, tid,
                                    pg, pb, cg, cb, tg, tb, out);
}

// round 12
// speedup vs baseline: 1.1083x; 1.0126x over previous
#include <cuda_runtime.h>

// BiologicalNormalization: 3 chained per-row LayerNorms (D=512), gathered
// per-sample affine params; trailing sigmoid-gated blend is the identity.
//
// R12: exactly R7 (ROWS=2/warp, 128 thr, lb(128,7) -> 72 regs, 28 warps/SM,
// full-warp shuffle reductions, remat'd param pointers) + __ldcg on x:
// streaming x bypasses L1 so L1 serves as a dedicated cache for the hot
// gathered gamma/beta tables (the only data with reuse).

#define B_DIM 2048
#define S_DIM 128
#define D_DIM 512
#define THREADS 128
#define WARPS 4
#define ROWS 2            // rows per warp -> 8 rows per block
#define SPLIT 16          // blocks per sample

__global__ __launch_bounds__(THREADS, 7)
void bionorm_kernel(const float* __restrict__ x,
                    const int* __restrict__ pathway_ids,
                    const int* __restrict__ compartment_ids,
                    const int* __restrict__ cell_type_ids,
                    const float* __restrict__ pg, const float* __restrict__ pb,
                    const float* __restrict__ cg, const float* __restrict__ cb,
                    const float* __restrict__ tg, const float* __restrict__ tb,
                    float* __restrict__ out)
{
    const int blk = blockIdx.x;
    const int b = blk >> 4;           // sample
    const int lane = threadIdx.x & 31;

    const int p_id = __ldg(pathway_ids + b);
    const int c_id = __ldg(compartment_ids + b);
    const int t_id = __ldg(cell_type_ids + b);

    const size_t elem0 = ((size_t)b * S_DIM
                        + ((blk & 15) * (WARPS * ROWS) + (threadIdx.x >> 5) * ROWS))
                        * D_DIM;
    const float4* __restrict__ xr = reinterpret_cast<const float4*>(x + elem0);

    // Front-batched load of 2 full rows: 8 independent LDG.128.CG
    // (L2-only; no L1 allocation -> L1 stays hot for params).
    float4 v[ROWS][4];
    #pragma unroll
    for (int r = 0; r < ROWS; r++)
        #pragma unroll
        for (int i = 0; i < 4; i++)
            v[r][i] = __ldcg(xr + r * (D_DIM / 4) + lane + 32 * i);

    const float inv_d = 1.0f / (float)D_DIM;
    const float eps = 1e-5f;

    #pragma unroll
    for (int p = 0; p < 3; p++) {
        // Param pointers rematerialized per pass from constant-bank bases.
        const float4* gvp;
        const float4* bvp;
        if (p == 0) {
            gvp = reinterpret_cast<const float4*>(pg + (size_t)p_id * D_DIM);
            bvp = reinterpret_cast<const float4*>(pb + (size_t)p_id * D_DIM);
        } else if (p == 1) {
            gvp = reinterpret_cast<const float4*>(cg + (size_t)c_id * D_DIM);
            bvp = reinterpret_cast<const float4*>(cb + (size_t)c_id * D_DIM);
        } else {
            gvp = reinterpret_cast<const float4*>(tg + (size_t)t_id * D_DIM);
            bvp = reinterpret_cast<const float4*>(tb + (size_t)t_id * D_DIM);
        }

        float sum[ROWS], sq[ROWS];
        #pragma unroll
        for (int r = 0; r < ROWS; r++) {
            float s = 0.f, q = 0.f;
            #pragma unroll
            for (int i = 0; i < 4; i++) {
                s += v[r][i].x + v[r][i].y + v[r][i].z + v[r][i].w;
                q = fmaf(v[r][i].x, v[r][i].x, q);
                q = fmaf(v[r][i].y, v[r][i].y, q);
                q = fmaf(v[r][i].z, v[r][i].z, q);
                q = fmaf(v[r][i].w, v[r][i].w, q);
            }
            sum[r] = s; sq[r] = q;
        }
        #pragma unroll
        for (int o = 16; o > 0; o >>= 1) {
            #pragma unroll
            for (int r = 0; r < ROWS; r++) {
                sum[r] += __shfl_xor_sync(0xffffffffu, sum[r], o);
                sq[r]  += __shfl_xor_sync(0xffffffffu, sq[r],  o);
            }
        }

        // a = rstd, c = -mean*rstd  ->  normalized = fma(v, a, c)
        float a[ROWS], c[ROWS];
        #pragma unroll
        for (int r = 0; r < ROWS; r++) {
            const float mean = sum[r] * inv_d;
            const float var = fmaf(-mean, mean, sq[r] * inv_d);
            a[r] = rsqrtf(var + eps);
            c[r] = -mean * a[r];
        }

        #pragma unroll
        for (int i = 0; i < 4; i++) {
            const float4 gg = __ldg(gvp + lane + 32 * i);
            const float4 bb = __ldg(bvp + lane + 32 * i);
            #pragma unroll
            for (int r = 0; r < ROWS; r++) {
                v[r][i].x = fmaf(fmaf(v[r][i].x, a[r], c[r]), gg.x, bb.x);
                v[r][i].y = fmaf(fmaf(v[r][i].y, a[r], c[r]), gg.y, bb.y);
                v[r][i].z = fmaf(fmaf(v[r][i].z, a[r], c[r]), gg.z, bb.z);
                v[r][i].w = fmaf(fmaf(v[r][i].w, a[r], c[r]), gg.w, bb.w);
            }
        }
    }

    float4* __restrict__ orow = reinterpret_cast<float4*>(out + elem0);
    #pragma unroll
    for (int r = 0; r < ROWS; r++)
        #pragma unroll
        for (int i = 0; i < 4; i++)
            orow[r * (D_DIM / 4) + lane + 32 * i] = v[r][i];
}

extern "C" void kernel_launch(void* const* d_in, const int* in_sizes, int n_in,
                              void* d_out, int out_size)
{
    const float* x  = (const float*)d_in[0];
    const int* pid  = (const int*)d_in[1];
    const int* cid  = (const int*)d_in[2];
    const int* tid  = (const int*)d_in[3];
    const float* pg = (const float*)d_in[4];
    const float* pb = (const float*)d_in[5];
    const float* cg = (const float*)d_in[6];
    const float* cb = (const float*)d_in[7];
    const float* tg = (const float*)d_in[8];
    const float* tb = (const float*)d_in[9];
    // d_in[10] = W, d_in[11] = b : unused (gated blend is the identity)
    float* out = (float*)d_out;

    dim3 grid(B_DIM * SPLIT);
    dim3 block(THREADS);
    bionorm_kernel<<<grid, block>>>(x, pid, cid, tid,
                                    pg, pb, cg, cb, tg, tb, out);
}